// round 10
// baseline (speedup 1.0000x reference)
#include <cuda_runtime.h>
#include <cuda_bf16.h>
#include <math.h>
#include <stdint.h>

#define NMAX 50000
#define EMAX 800000
#define H 128

// Scratch (device globals — no allocation anywhere)
__device__ int    g_cnt[NMAX];
__device__ float  g_dis[NMAX];
__device__ int    g_rowptr[NMAX + 1];
__device__ int    g_bsum[64];
__device__ int    g_csrc[EMAX];
__device__ float  g_cnrm[EMAX];
__device__ float4 g_B0[NMAX * 32];
__device__ float4 g_B1[NMAX * 32];
__device__ float4 g_B2[NMAX * 32];

// ===========================================================================
// bf16-split mma.sync GEMM: C[M x 128] = A[M x 128] @ W[128 x 128]
//   A = Ahi + Alo, W = Whi + Wlo (bf16 each);  D = Ahi Whi + Ahi Wlo + Alo Whi
// persistent, 256 threads, 2 CTAs/SM, W resident in SMEM per CTA
// ===========================================================================

// SMEM layout (bytes):
//   Wsm: 2 terms x [128 n][136 k] bf16   -> term stride 34816, row stride 272
//   Asm: 2 bufs x 2 terms x [128 m][24 k] bf16 -> (buf,term) stride 6144, row 48
#define WS_OFF   0
#define W_TERM   34816
#define AS_OFF   69632
#define AS_BT    6144
#define SM_BYTES 94208   // 69632 + 4*6144

__device__ __forceinline__ void mma_bf16(float4& d, const uint32_t* a,
                                         uint32_t b0, uint32_t b1) {
    asm volatile(
        "mma.sync.aligned.m16n8k16.row.col.f32.bf16.bf16.f32 "
        "{%0,%1,%2,%3}, {%4,%5,%6,%7}, {%8,%9}, {%0,%1,%2,%3};\n"
        : "+f"(d.x), "+f"(d.y), "+f"(d.z), "+f"(d.w)
        : "r"(a[0]), "r"(a[1]), "r"(a[2]), "r"(a[3]), "r"(b0), "r"(b1));
}

__device__ __forceinline__ void split4(float4 v, uint2& h, uint2& l) {
    __nv_bfloat162 hxy = __floats2bfloat162_rn(v.x, v.y);
    __nv_bfloat162 hzw = __floats2bfloat162_rn(v.z, v.w);
    float2 fxy = __bfloat1622float2(hxy);
    float2 fzw = __bfloat1622float2(hzw);
    __nv_bfloat162 lxy = __floats2bfloat162_rn(v.x - fxy.x, v.y - fxy.y);
    __nv_bfloat162 lzw = __floats2bfloat162_rn(v.z - fzw.x, v.w - fzw.y);
    h.x = *(uint32_t*)&hxy; h.y = *(uint32_t*)&hzw;
    l.x = *(uint32_t*)&lxy; l.y = *(uint32_t*)&lzw;
}

__global__ __launch_bounds__(256, 2) void k_gemm_bf16x3(
    const float* __restrict__ A, const float* __restrict__ W,
    float* __restrict__ C, int M, int ntiles)
{
    extern __shared__ char sm[];
    const int tid  = threadIdx.x;
    const int lane = tid & 31;
    const int wid  = tid >> 5;
    const int wm   = wid & 3;       // warp row (4 x 32 = 128 M)
    const int wn   = wid >> 2;      // warp col (2 x 64 = 128 N)
    const int g    = lane >> 2;     // group id 0..7
    const int tg   = lane & 3;      // thread-in-group

    // ---- W -> bf16 hi/lo in SMEM (once per CTA). W[k][n] stored as Wsm[n][k].
    for (int idx = tid; idx < 128 * 128; idx += 256) {
        int k = idx >> 7, n = idx & 127;
        float w = __ldg(W + idx);
        __nv_bfloat16 hb = __float2bfloat16_rn(w);
        __nv_bfloat16 lb = __float2bfloat16_rn(w - __bfloat162float(hb));
        *(__nv_bfloat16*)(sm + WS_OFF + (size_t)n * 272 + k * 2)          = hb;
        *(__nv_bfloat16*)(sm + WS_OFF + W_TERM + (size_t)n * 272 + k * 2) = lb;
    }
    __syncthreads();

    const int srow = tid >> 1;            // staging: A row this thread loads
    const int sk   = (tid & 1) * 8;       // k offset (8 floats per thread)

    for (int t = blockIdx.x; t < ntiles; t += gridDim.x) {
        const int m0 = t << 7;

        float4 c[2][8];
#pragma unroll
        for (int mt = 0; mt < 2; mt++)
#pragma unroll
            for (int nt = 0; nt < 8; nt++) c[mt][nt] = make_float4(0.f, 0.f, 0.f, 0.f);

        const int  grow = m0 + srow;
        const bool rok  = grow < M;
        const float* ap = A + (size_t)grow * H + sk;
        const float4 z4 = make_float4(0.f, 0.f, 0.f, 0.f);

        // prefetch chunk 0 -> stash into buf 0
        float4 s0 = rok ? *(const float4*)(ap)     : z4;
        float4 s1 = rok ? *(const float4*)(ap + 4) : z4;
        {
            uint2 h, l;
            char* b = sm + AS_OFF + (size_t)srow * 48 + sk * 2;
            split4(s0, h, l);
            *(uint2*)(b)          = h;  *(uint2*)(b + AS_BT)          = l;
            split4(s1, h, l);
            *(uint2*)(b + 8)      = h;  *(uint2*)(b + AS_BT + 8)      = l;
        }

#pragma unroll
        for (int kc = 0; kc < 8; kc++) {
            if (kc < 7) {
                const float* p = ap + (kc + 1) * 16;
                s0 = rok ? *(const float4*)(p)     : z4;
                s1 = rok ? *(const float4*)(p + 4) : z4;
            }
            __syncthreads();
            const int buf = kc & 1;

            // A fragments (hi/lo), 2 m-subtiles
            uint32_t afh[2][4], afl[2][4];
#pragma unroll
            for (int mt = 0; mt < 2; mt++) {
                int m = wm * 32 + mt * 16 + g;
                const char* b0 = sm + AS_OFF + (size_t)(buf * 2) * AS_BT + (size_t)m * 48 + tg * 4;
                afh[mt][0] = *(const uint32_t*)(b0);
                afh[mt][1] = *(const uint32_t*)(b0 + 8 * 48);
                afh[mt][2] = *(const uint32_t*)(b0 + 16);
                afh[mt][3] = *(const uint32_t*)(b0 + 8 * 48 + 16);
                const char* b1 = b0 + AS_BT;
                afl[mt][0] = *(const uint32_t*)(b1);
                afl[mt][1] = *(const uint32_t*)(b1 + 8 * 48);
                afl[mt][2] = *(const uint32_t*)(b1 + 16);
                afl[mt][3] = *(const uint32_t*)(b1 + 8 * 48 + 16);
            }

#pragma unroll
            for (int nt = 0; nt < 8; nt++) {
                int n = wn * 64 + nt * 8 + g;
                const char* wb = sm + WS_OFF + (size_t)n * 272 + kc * 32 + tg * 4;
                uint32_t bh0 = *(const uint32_t*)(wb);
                uint32_t bh1 = *(const uint32_t*)(wb + 16);
                uint32_t bl0 = *(const uint32_t*)(wb + W_TERM);
                uint32_t bl1 = *(const uint32_t*)(wb + W_TERM + 16);
                mma_bf16(c[0][nt], afh[0], bh0, bh1);
                mma_bf16(c[1][nt], afh[1], bh0, bh1);
                mma_bf16(c[0][nt], afh[0], bl0, bl1);
                mma_bf16(c[1][nt], afh[1], bl0, bl1);
                mma_bf16(c[0][nt], afl[0], bh0, bh1);
                mma_bf16(c[1][nt], afl[1], bh0, bh1);
            }

            if (kc < 7) {
                uint2 h, l;
                char* b = sm + AS_OFF + (size_t)(((kc + 1) & 1) * 2) * AS_BT
                        + (size_t)srow * 48 + sk * 2;
                split4(s0, h, l);
                *(uint2*)(b)     = h;  *(uint2*)(b + AS_BT)     = l;
                split4(s1, h, l);
                *(uint2*)(b + 8) = h;  *(uint2*)(b + AS_BT + 8) = l;
            }
        }

        // epilogue: write fp32 C
#pragma unroll
        for (int mt = 0; mt < 2; mt++) {
            int r0 = m0 + wm * 32 + mt * 16 + g;
#pragma unroll
            for (int nt = 0; nt < 8; nt++) {
                int col = wn * 64 + nt * 8 + tg * 2;
                float4 v = c[mt][nt];
                if (r0 < M)     *(float2*)(C + (size_t)r0 * H + col)       = make_float2(v.x, v.y);
                if (r0 + 8 < M) *(float2*)(C + (size_t)(r0 + 8) * H + col) = make_float2(v.z, v.w);
            }
        }
    }
}

// ===========================================================================
// CSR build
// ===========================================================================
__global__ void k_zero(int* __restrict__ p, int n) {
    int i = blockIdx.x * blockDim.x + threadIdx.x;
    if (i < n) p[i] = 0;
}
__global__ void k_hist(const int* __restrict__ dst, int* __restrict__ cnt, int E) {
    int i = blockIdx.x * blockDim.x + threadIdx.x;
    if (i < E) atomicAdd(&cnt[dst[i]], 1);
}
__global__ void k_calc_dis(const int* __restrict__ cnt, float* __restrict__ dis, int n) {
    int i = blockIdx.x * blockDim.x + threadIdx.x;
    if (i < n) dis[i] = rsqrtf((float)(cnt[i] + 1));
}
__global__ void k_scan_a(const int* __restrict__ cnt, int* __restrict__ out,
                         int* __restrict__ bsum, int n) {
    __shared__ int sh[256];
    int tid = threadIdx.x;
    int idx0 = blockIdx.x * 1024 + tid * 4;
    int it[4];
#pragma unroll
    for (int i = 0; i < 4; i++) it[i] = (idx0 + i < n) ? cnt[idx0 + i] : 0;
    int sum = it[0] + it[1] + it[2] + it[3];
    sh[tid] = sum;
    __syncthreads();
#pragma unroll
    for (int off = 1; off < 256; off <<= 1) {
        int v = (tid >= off) ? sh[tid - off] : 0;
        __syncthreads();
        sh[tid] += v;
        __syncthreads();
    }
    int run = sh[tid] - sum;
#pragma unroll
    for (int i = 0; i < 4; i++) {
        if (idx0 + i < n) out[idx0 + i] = run;
        run += it[i];
    }
    if (tid == 255) bsum[blockIdx.x] = sh[255];
}
__global__ void k_scan_b(int* __restrict__ bsum, int nb) {
    if (threadIdx.x == 0) {
        int acc = 0;
        for (int i = 0; i < nb; i++) { int v = bsum[i]; bsum[i] = acc; acc += v; }
    }
}
__global__ void k_scan_c(int* __restrict__ out, const int* __restrict__ bsum, int n, int E) {
    int i = blockIdx.x * blockDim.x + threadIdx.x;
    if (i < n) out[i] += bsum[i >> 10];
    if (i == 0) out[n] = E;
}
__global__ void k_fill(const int* __restrict__ src, const int* __restrict__ dst,
                       const float* __restrict__ dis, const int* __restrict__ rowptr,
                       int* __restrict__ fill, int* __restrict__ csrc,
                       float* __restrict__ cnrm, int E) {
    int e = blockIdx.x * blockDim.x + threadIdx.x;
    if (e >= E) return;
    int s = src[e], d = dst[e];
    int pos = rowptr[d] + atomicAdd(&fill[d], 1);
    csrc[pos] = s;
    cnrm[pos] = dis[s] * dis[d];
}

// ===========================================================================
// Fused gather + self-loop + bias + ELU (warp per node)
// ===========================================================================
__global__ __launch_bounds__(256) void k_gather(
    const int* __restrict__ rowptr, const int* __restrict__ csrc,
    const float* __restrict__ cnrm, const float* __restrict__ dis,
    const float4* __restrict__ h2, const float4* __restrict__ b4,
    float4* __restrict__ out, int n)
{
    int gt   = blockIdx.x * blockDim.x + threadIdx.x;
    int v    = gt >> 5;
    int lane = threadIdx.x & 31;
    if (v >= n) return;

    float s = dis[v];
    float selfw = s * s;
    float4 acc = __ldg(h2 + (size_t)v * 32 + lane);
    acc.x *= selfw; acc.y *= selfw; acc.z *= selfw; acc.w *= selfw;

    int j   = __ldg(rowptr + v);
    int end = __ldg(rowptr + v + 1);

    for (; j + 1 < end; j += 2) {
        int   s0 = __ldg(csrc + j),     s1 = __ldg(csrc + j + 1);
        float w0 = __ldg(cnrm + j),     w1 = __ldg(cnrm + j + 1);
        float4 t0 = __ldg(h2 + (size_t)s0 * 32 + lane);
        float4 t1 = __ldg(h2 + (size_t)s1 * 32 + lane);
        acc.x = fmaf(t0.x, w0, acc.x); acc.x = fmaf(t1.x, w1, acc.x);
        acc.y = fmaf(t0.y, w0, acc.y); acc.y = fmaf(t1.y, w1, acc.y);
        acc.z = fmaf(t0.z, w0, acc.z); acc.z = fmaf(t1.z, w1, acc.z);
        acc.w = fmaf(t0.w, w0, acc.w); acc.w = fmaf(t1.w, w1, acc.w);
    }
    if (j < end) {
        int   s0 = __ldg(csrc + j);
        float w0 = __ldg(cnrm + j);
        float4 t0 = __ldg(h2 + (size_t)s0 * 32 + lane);
        acc.x = fmaf(t0.x, w0, acc.x);
        acc.y = fmaf(t0.y, w0, acc.y);
        acc.z = fmaf(t0.z, w0, acc.z);
        acc.w = fmaf(t0.w, w0, acc.w);
    }

    float4 b = __ldg(b4 + lane);
    acc.x += b.x; acc.y += b.y; acc.z += b.z; acc.w += b.w;
    acc.x = acc.x > 0.f ? acc.x : expm1f(acc.x);
    acc.y = acc.y > 0.f ? acc.y : expm1f(acc.y);
    acc.z = acc.z > 0.f ? acc.z : expm1f(acc.z);
    acc.w = acc.w > 0.f ? acc.w : expm1f(acc.w);
    out[(size_t)v * 32 + lane] = acc;
}

// ===========================================================================
// final projection (warp per node)
// ===========================================================================
__global__ void k_final(const float4* __restrict__ h, const float4* __restrict__ Wl4,
                        const float* __restrict__ bl, float* __restrict__ out, int n) {
    int gt   = blockIdx.x * blockDim.x + threadIdx.x;
    int v    = gt >> 5;
    int lane = threadIdx.x & 31;
    if (v >= n) return;
    float4 hv = __ldg(h + (size_t)v * 32 + lane);
    float4 wv = __ldg(Wl4 + lane);
    float p = hv.x * wv.x + hv.y * wv.y + hv.z * wv.z + hv.w * wv.w;
#pragma unroll
    for (int o = 16; o > 0; o >>= 1) p += __shfl_xor_sync(0xffffffff, p, o);
    if (lane == 0) out[v] = p + __ldg(bl);
}

// ===========================================================================
extern "C" void kernel_launch(void* const* d_in, const int* in_sizes, int n_in,
                              void* d_out, int out_size) {
    const float* x  = (const float*)d_in[0];
    const float* Ws = (const float*)d_in[1];
    const float* bs = (const float*)d_in[2];
    const float* Wl = (const float*)d_in[3];
    const float* bl = (const float*)d_in[4];
    const int*   ei = (const int*)d_in[5];

    int n = in_sizes[0] / H;      // 50000
    int E = in_sizes[5] / 2;      // 800000
    const int* src = ei;
    const int* dst = ei + E;

    int *cnt, *rowptr, *bsum, *csrc;
    float *dis, *cnrm;
    float4 *B0, *B1, *B2;
    cudaGetSymbolAddress((void**)&cnt,    g_cnt);
    cudaGetSymbolAddress((void**)&dis,    g_dis);
    cudaGetSymbolAddress((void**)&rowptr, g_rowptr);
    cudaGetSymbolAddress((void**)&bsum,   g_bsum);
    cudaGetSymbolAddress((void**)&csrc,   g_csrc);
    cudaGetSymbolAddress((void**)&cnrm,   g_cnrm);
    cudaGetSymbolAddress((void**)&B0,     g_B0);
    cudaGetSymbolAddress((void**)&B1,     g_B1);
    cudaGetSymbolAddress((void**)&B2,     g_B2);

    static int sms = 0;
    if (sms <= 0) {
        cudaDeviceGetAttribute(&sms, cudaDevAttrMultiProcessorCount, 0);
        if (sms <= 0) sms = 148;
    }

    cudaFuncSetAttribute(k_gemm_bf16x3, cudaFuncAttributeMaxDynamicSharedMemorySize, SM_BYTES);

    const int T = 256;
    int nb_n = (n + T - 1) / T;
    int nb_E = (E + T - 1) / T;
    int nb_scan = (n + 1023) / 1024;

    // ---- CSR build ----
    k_zero<<<nb_n, T>>>(cnt, n);
    k_hist<<<nb_E, T>>>(dst, cnt, E);
    k_calc_dis<<<nb_n, T>>>(cnt, dis, n);
    k_scan_a<<<nb_scan, T>>>(cnt, rowptr, bsum, n);
    k_scan_b<<<1, 32>>>(bsum, nb_scan);
    k_scan_c<<<nb_n, T>>>(rowptr, bsum, n, E);
    k_zero<<<nb_n, T>>>(cnt, n);
    k_fill<<<nb_E, T>>>(src, dst, dis, rowptr, cnt, csrc, cnrm, E);

    int ntiles = (n + 127) >> 7;
    int gemm_grid = 2 * sms;
    if (gemm_grid > ntiles) gemm_grid = ntiles;
    int gather_blocks = (n * 32 + T - 1) / T;

    // ---- 3 GCN layers ----
    for (int l = 0; l < 3; l++) {
        const float* hcur = (l == 0) ? x : (const float*)((l == 1) ? B1 : B2);
        float4* hout = (l == 1) ? B2 : B1;

        k_gemm_bf16x3<<<gemm_grid, T, SM_BYTES>>>(hcur, Ws + (size_t)l * H * H, (float*)B0, n, ntiles);
        k_gather<<<gather_blocks, T>>>(rowptr, csrc, cnrm, dis, B0,
                                       (const float4*)(bs + (size_t)l * H), hout, n);
    }

    k_final<<<gather_blocks, T>>>(B1, (const float4*)Wl, bl, (float*)d_out, n);
}

// round 12
// speedup vs baseline: 1.1847x; 1.1847x over previous
#include <cuda_runtime.h>
#include <cuda_bf16.h>
#include <math.h>
#include <stdint.h>

#define NMAX 50000
#define EMAX 800000
#define H 128

// Scratch (device globals — no allocation anywhere)
__device__ int    g_cnt[NMAX];
__device__ float  g_dis[NMAX];
__device__ int    g_rowptr[NMAX + 1];
__device__ int    g_bsum[64];
__device__ int    g_csrc[EMAX];
__device__ float  g_cnrm[EMAX];
__device__ float4 g_B0[NMAX * 32];
__device__ float4 g_B1[NMAX * 32];
__device__ float4 g_B2[NMAX * 32];

// ===========================================================================
// Dual-role GEMM: C[M x 128] = A[M x 128] @ W[128 x 128]
//   role F (bid <  148): fp32 FFMA SGEMM  — tiles [S, ntiles)
//   role H (bid >= 148): bf16x3 mma.sync — tiles [0, S)
// grid = 296, 256 thr, 94KB dyn smem -> 2 CTAs/SM, one of each role per SM.
// ===========================================================================

// H-role SMEM layout (bytes within dynamic smem):
#define WS_OFF   0
#define W_TERM   34816
#define AS_OFF   69632
#define AS_BT    6144
#define SM_BYTES 94208

__device__ __forceinline__ void mma_bf16(float4& d, const uint32_t* a,
                                         uint32_t b0, uint32_t b1) {
    asm volatile(
        "mma.sync.aligned.m16n8k16.row.col.f32.bf16.bf16.f32 "
        "{%0,%1,%2,%3}, {%4,%5,%6,%7}, {%8,%9}, {%0,%1,%2,%3};\n"
        : "+f"(d.x), "+f"(d.y), "+f"(d.z), "+f"(d.w)
        : "r"(a[0]), "r"(a[1]), "r"(a[2]), "r"(a[3]), "r"(b0), "r"(b1));
}

__device__ __forceinline__ void split4(float4 v, uint2& h, uint2& l) {
    __nv_bfloat162 hxy = __floats2bfloat162_rn(v.x, v.y);
    __nv_bfloat162 hzw = __floats2bfloat162_rn(v.z, v.w);
    float2 fxy = __bfloat1622float2(hxy);
    float2 fzw = __bfloat1622float2(hzw);
    __nv_bfloat162 lxy = __floats2bfloat162_rn(v.x - fxy.x, v.y - fxy.y);
    __nv_bfloat162 lzw = __floats2bfloat162_rn(v.z - fzw.x, v.w - fzw.y);
    h.x = *(uint32_t*)&hxy; h.y = *(uint32_t*)&hzw;
    l.x = *(uint32_t*)&lxy; l.y = *(uint32_t*)&lzw;
}

// ---- role H: bf16x3 mma path (verbatim from passing R10 kernel) ----
__device__ void gemm_role_hmma(char* sm, const float* __restrict__ A,
                               const float* __restrict__ W, float* __restrict__ C,
                               int M, int S, int hbid)
{
    const int tid  = threadIdx.x;
    const int lane = tid & 31;
    const int wid  = tid >> 5;
    const int wm   = wid & 3;
    const int wn   = wid >> 2;
    const int g    = lane >> 2;
    const int tg   = lane & 3;

    // W -> bf16 hi/lo in SMEM (once). W[k][n] stored as Wsm[n][k].
    for (int idx = tid; idx < 128 * 128; idx += 256) {
        int k = idx >> 7, n = idx & 127;
        float w = __ldg(W + idx);
        __nv_bfloat16 hb = __float2bfloat16_rn(w);
        __nv_bfloat16 lb = __float2bfloat16_rn(w - __bfloat162float(hb));
        *(__nv_bfloat16*)(sm + WS_OFF + (size_t)n * 272 + k * 2)          = hb;
        *(__nv_bfloat16*)(sm + WS_OFF + W_TERM + (size_t)n * 272 + k * 2) = lb;
    }
    __syncthreads();

    const int srow = tid >> 1;
    const int sk   = (tid & 1) * 8;

    for (int t = hbid; t < S; t += 148) {
        const int m0 = t << 7;

        float4 c[2][8];
#pragma unroll
        for (int mt = 0; mt < 2; mt++)
#pragma unroll
            for (int nt = 0; nt < 8; nt++) c[mt][nt] = make_float4(0.f, 0.f, 0.f, 0.f);

        const int  grow = m0 + srow;
        const bool rok  = grow < M;
        const float* ap = A + (size_t)grow * H + sk;
        const float4 z4 = make_float4(0.f, 0.f, 0.f, 0.f);

        float4 s0 = rok ? *(const float4*)(ap)     : z4;
        float4 s1 = rok ? *(const float4*)(ap + 4) : z4;
        {
            uint2 h, l;
            char* b = sm + AS_OFF + (size_t)srow * 48 + sk * 2;
            split4(s0, h, l);
            *(uint2*)(b)     = h;  *(uint2*)(b + AS_BT)     = l;
            split4(s1, h, l);
            *(uint2*)(b + 8) = h;  *(uint2*)(b + AS_BT + 8) = l;
        }

#pragma unroll
        for (int kc = 0; kc < 8; kc++) {
            if (kc < 7) {
                const float* p = ap + (kc + 1) * 16;
                s0 = rok ? *(const float4*)(p)     : z4;
                s1 = rok ? *(const float4*)(p + 4) : z4;
            }
            __syncthreads();
            const int buf = kc & 1;

            uint32_t afh[2][4], afl[2][4];
#pragma unroll
            for (int mt = 0; mt < 2; mt++) {
                int m = wm * 32 + mt * 16 + g;
                const char* b0 = sm + AS_OFF + (size_t)(buf * 2) * AS_BT + (size_t)m * 48 + tg * 4;
                afh[mt][0] = *(const uint32_t*)(b0);
                afh[mt][1] = *(const uint32_t*)(b0 + 8 * 48);
                afh[mt][2] = *(const uint32_t*)(b0 + 16);
                afh[mt][3] = *(const uint32_t*)(b0 + 8 * 48 + 16);
                const char* b1 = b0 + AS_BT;
                afl[mt][0] = *(const uint32_t*)(b1);
                afl[mt][1] = *(const uint32_t*)(b1 + 8 * 48);
                afl[mt][2] = *(const uint32_t*)(b1 + 16);
                afl[mt][3] = *(const uint32_t*)(b1 + 8 * 48 + 16);
            }

#pragma unroll
            for (int nt = 0; nt < 8; nt++) {
                int n = wn * 64 + nt * 8 + g;
                const char* wb = sm + WS_OFF + (size_t)n * 272 + kc * 32 + tg * 4;
                uint32_t bh0 = *(const uint32_t*)(wb);
                uint32_t bh1 = *(const uint32_t*)(wb + 16);
                uint32_t bl0 = *(const uint32_t*)(wb + W_TERM);
                uint32_t bl1 = *(const uint32_t*)(wb + W_TERM + 16);
                mma_bf16(c[0][nt], afh[0], bh0, bh1);
                mma_bf16(c[1][nt], afh[1], bh0, bh1);
                mma_bf16(c[0][nt], afh[0], bl0, bl1);
                mma_bf16(c[1][nt], afh[1], bl0, bl1);
                mma_bf16(c[0][nt], afl[0], bh0, bh1);
                mma_bf16(c[1][nt], afl[1], bh0, bh1);
            }

            if (kc < 7) {
                uint2 h, l;
                char* b = sm + AS_OFF + (size_t)(((kc + 1) & 1) * 2) * AS_BT
                        + (size_t)srow * 48 + sk * 2;
                split4(s0, h, l);
                *(uint2*)(b)     = h;  *(uint2*)(b + AS_BT)     = l;
                split4(s1, h, l);
                *(uint2*)(b + 8) = h;  *(uint2*)(b + AS_BT + 8) = l;
            }
        }

#pragma unroll
        for (int mt = 0; mt < 2; mt++) {
            int r0 = m0 + wm * 32 + mt * 16 + g;
#pragma unroll
            for (int nt = 0; nt < 8; nt++) {
                int col = wn * 64 + nt * 8 + tg * 2;
                float4 v = c[mt][nt];
                if (r0 < M)     *(float2*)(C + (size_t)r0 * H + col)       = make_float2(v.x, v.y);
                if (r0 + 8 < M) *(float2*)(C + (size_t)(r0 + 8) * H + col) = make_float2(v.z, v.w);
            }
        }
        __syncthreads();
    }
}

// ---- role F: fp32 FFMA SGEMM (verbatim from passing R5 kernel) ----
__device__ void gemm_role_ffma(char* smraw, const float* __restrict__ A,
                               const float* __restrict__ W, float* __restrict__ C,
                               int M, int S, int ntiles, int fbid)
{
    float (*As)[128] = (float (*)[128])(smraw);            // [16][128]
    float (*Bs)[128] = (float (*)[128])(smraw + 8192);     // [16][128]

    const int tid = threadIdx.x;
    const int tx  = tid & 15;
    const int ty  = tid >> 4;

    const int ar = tid >> 2;
    const int ac = (tid & 3) << 2;
    const int br = tid >> 5;
    const int bc = (tid & 31) << 2;

    for (int t = S + fbid; t < ntiles; t += 148) {
        const int m0 = t << 7;

        float acc[8][8];
#pragma unroll
        for (int i = 0; i < 8; i++)
#pragma unroll
            for (int j = 0; j < 8; j++) acc[i][j] = 0.0f;

        for (int k0 = 0; k0 < 128; k0 += 16) {
#pragma unroll
            for (int i = 0; i < 2; i++) {
                int row = m0 + ar + i * 64;
                float4 v = make_float4(0.f, 0.f, 0.f, 0.f);
                if (row < M) v = *(const float4*)(A + (size_t)row * H + k0 + ac);
                As[ac + 0][ar + i * 64] = v.x;
                As[ac + 1][ar + i * 64] = v.y;
                As[ac + 2][ar + i * 64] = v.z;
                As[ac + 3][ar + i * 64] = v.w;
            }
#pragma unroll
            for (int i = 0; i < 2; i++) {
                int kk = br + i * 8;
                *(float4*)&Bs[kk][bc] = *(const float4*)(W + (size_t)(k0 + kk) * H + bc);
            }
            __syncthreads();

#pragma unroll
            for (int k = 0; k < 16; k++) {
                float a[8], b[8];
                *(float4*)(a)     = *(const float4*)&As[k][ty * 8];
                *(float4*)(a + 4) = *(const float4*)&As[k][ty * 8 + 4];
                *(float4*)(b)     = *(const float4*)&Bs[k][tx * 8];
                *(float4*)(b + 4) = *(const float4*)&Bs[k][tx * 8 + 4];
#pragma unroll
                for (int i = 0; i < 8; i++)
#pragma unroll
                    for (int j = 0; j < 8; j++)
                        acc[i][j] = fmaf(a[i], b[j], acc[i][j]);
            }
            __syncthreads();
        }

#pragma unroll
        for (int i = 0; i < 8; i++) {
            int row = m0 + ty * 8 + i;
            if (row < M) {
                *(float4*)(C + (size_t)row * H + tx * 8)     = make_float4(acc[i][0], acc[i][1], acc[i][2], acc[i][3]);
                *(float4*)(C + (size_t)row * H + tx * 8 + 4) = make_float4(acc[i][4], acc[i][5], acc[i][6], acc[i][7]);
            }
        }
    }
}

__global__ __launch_bounds__(256, 2) void k_gemm_dual(
    const float* __restrict__ A, const float* __restrict__ W,
    float* __restrict__ C, int M, int ntiles, int S)
{
    extern __shared__ char sm[];
    if (blockIdx.x >= 148) gemm_role_hmma(sm, A, W, C, M, S, blockIdx.x - 148);
    else                   gemm_role_ffma(sm, A, W, C, M, S, ntiles, blockIdx.x);
}

// ===========================================================================
// CSR build
// ===========================================================================
__global__ void k_zero(int* __restrict__ p, int n) {
    int i = blockIdx.x * blockDim.x + threadIdx.x;
    if (i < n) p[i] = 0;
}
__global__ void k_hist(const int* __restrict__ dst, int* __restrict__ cnt, int E) {
    int i = blockIdx.x * blockDim.x + threadIdx.x;
    if (i < E) atomicAdd(&cnt[dst[i]], 1);
}
// scan (exclusive) + dis = rsqrt(cnt+1) fused
__global__ void k_scan_a(const int* __restrict__ cnt, int* __restrict__ out,
                         int* __restrict__ bsum, float* __restrict__ dis, int n) {
    __shared__ int sh[256];
    int tid = threadIdx.x;
    int idx0 = blockIdx.x * 1024 + tid * 4;
    int it[4];
#pragma unroll
    for (int i = 0; i < 4; i++) {
        it[i] = (idx0 + i < n) ? cnt[idx0 + i] : 0;
        if (idx0 + i < n) dis[idx0 + i] = rsqrtf((float)(it[i] + 1));
    }
    int sum = it[0] + it[1] + it[2] + it[3];
    sh[tid] = sum;
    __syncthreads();
#pragma unroll
    for (int off = 1; off < 256; off <<= 1) {
        int v = (tid >= off) ? sh[tid - off] : 0;
        __syncthreads();
        sh[tid] += v;
        __syncthreads();
    }
    int run = sh[tid] - sum;
#pragma unroll
    for (int i = 0; i < 4; i++) {
        if (idx0 + i < n) out[idx0 + i] = run;
        run += it[i];
    }
    if (tid == 255) bsum[blockIdx.x] = sh[255];
}
__global__ void k_scan_b(int* __restrict__ bsum, int nb) {
    if (threadIdx.x == 0) {
        int acc = 0;
        for (int i = 0; i < nb; i++) { int v = bsum[i]; bsum[i] = acc; acc += v; }
    }
}
__global__ void k_scan_c(int* __restrict__ out, const int* __restrict__ bsum, int n, int E) {
    int i = blockIdx.x * blockDim.x + threadIdx.x;
    if (i < n) out[i] += bsum[i >> 10];
    if (i == 0) out[n] = E;
}
__global__ void k_fill(const int* __restrict__ src, const int* __restrict__ dst,
                       const float* __restrict__ dis, const int* __restrict__ rowptr,
                       int* __restrict__ fill, int* __restrict__ csrc,
                       float* __restrict__ cnrm, int E) {
    int e = blockIdx.x * blockDim.x + threadIdx.x;
    if (e >= E) return;
    int s = src[e], d = dst[e];
    int pos = rowptr[d] + atomicAdd(&fill[d], 1);
    csrc[pos] = s;
    cnrm[pos] = dis[s] * dis[d];
}

// ===========================================================================
// Fused gather + self-loop + bias + ELU (warp per node)
// ===========================================================================
__device__ __forceinline__ float4 gather_acc(
    const int* __restrict__ rowptr, const int* __restrict__ csrc,
    const float* __restrict__ cnrm, const float* __restrict__ dis,
    const float4* __restrict__ h2, const float4* __restrict__ b4,
    int v, int lane)
{
    float s = dis[v];
    float selfw = s * s;
    float4 acc = __ldg(h2 + (size_t)v * 32 + lane);
    acc.x *= selfw; acc.y *= selfw; acc.z *= selfw; acc.w *= selfw;

    int j   = __ldg(rowptr + v);
    int end = __ldg(rowptr + v + 1);

    for (; j + 1 < end; j += 2) {
        int   s0 = __ldg(csrc + j),     s1 = __ldg(csrc + j + 1);
        float w0 = __ldg(cnrm + j),     w1 = __ldg(cnrm + j + 1);
        float4 t0 = __ldg(h2 + (size_t)s0 * 32 + lane);
        float4 t1 = __ldg(h2 + (size_t)s1 * 32 + lane);
        acc.x = fmaf(t0.x, w0, acc.x); acc.x = fmaf(t1.x, w1, acc.x);
        acc.y = fmaf(t0.y, w0, acc.y); acc.y = fmaf(t1.y, w1, acc.y);
        acc.z = fmaf(t0.z, w0, acc.z); acc.z = fmaf(t1.z, w1, acc.z);
        acc.w = fmaf(t0.w, w0, acc.w); acc.w = fmaf(t1.w, w1, acc.w);
    }
    if (j < end) {
        int   s0 = __ldg(csrc + j);
        float w0 = __ldg(cnrm + j);
        float4 t0 = __ldg(h2 + (size_t)s0 * 32 + lane);
        acc.x = fmaf(t0.x, w0, acc.x);
        acc.y = fmaf(t0.y, w0, acc.y);
        acc.z = fmaf(t0.z, w0, acc.z);
        acc.w = fmaf(t0.w, w0, acc.w);
    }

    float4 b = __ldg(b4 + lane);
    acc.x += b.x; acc.y += b.y; acc.z += b.z; acc.w += b.w;
    acc.x = acc.x > 0.f ? acc.x : expm1f(acc.x);
    acc.y = acc.y > 0.f ? acc.y : expm1f(acc.y);
    acc.z = acc.z > 0.f ? acc.z : expm1f(acc.z);
    acc.w = acc.w > 0.f ? acc.w : expm1f(acc.w);
    return acc;
}

__global__ __launch_bounds__(256) void k_gather(
    const int* __restrict__ rowptr, const int* __restrict__ csrc,
    const float* __restrict__ cnrm, const float* __restrict__ dis,
    const float4* __restrict__ h2, const float4* __restrict__ b4,
    float4* __restrict__ out, int n)
{
    int gt   = blockIdx.x * blockDim.x + threadIdx.x;
    int v    = gt >> 5;
    int lane = threadIdx.x & 31;
    if (v >= n) return;
    out[(size_t)v * 32 + lane] =
        gather_acc(rowptr, csrc, cnrm, dis, h2, b4, v, lane);
}

// last layer: gather + bias + ELU + dot(Wl) + bl  (no intermediate write)
__global__ __launch_bounds__(256) void k_gather_final(
    const int* __restrict__ rowptr, const int* __restrict__ csrc,
    const float* __restrict__ cnrm, const float* __restrict__ dis,
    const float4* __restrict__ h2, const float4* __restrict__ b4,
    const float4* __restrict__ Wl4, const float* __restrict__ bl,
    float* __restrict__ out, int n)
{
    int gt   = blockIdx.x * blockDim.x + threadIdx.x;
    int v    = gt >> 5;
    int lane = threadIdx.x & 31;
    if (v >= n) return;
    float4 acc = gather_acc(rowptr, csrc, cnrm, dis, h2, b4, v, lane);
    float4 wv  = __ldg(Wl4 + lane);
    float p = acc.x * wv.x + acc.y * wv.y + acc.z * wv.z + acc.w * wv.w;
#pragma unroll
    for (int o = 16; o > 0; o >>= 1) p += __shfl_xor_sync(0xffffffff, p, o);
    if (lane == 0) out[v] = p + __ldg(bl);
}

// ===========================================================================
extern "C" void kernel_launch(void* const* d_in, const int* in_sizes, int n_in,
                              void* d_out, int out_size) {
    const float* x  = (const float*)d_in[0];
    const float* Ws = (const float*)d_in[1];
    const float* bs = (const float*)d_in[2];
    const float* Wl = (const float*)d_in[3];
    const float* bl = (const float*)d_in[4];
    const int*   ei = (const int*)d_in[5];

    int n = in_sizes[0] / H;      // 50000
    int E = in_sizes[5] / 2;      // 800000
    const int* src = ei;
    const int* dst = ei + E;

    int *cnt, *rowptr, *bsum, *csrc;
    float *dis, *cnrm;
    float4 *B0, *B1, *B2;
    cudaGetSymbolAddress((void**)&cnt,    g_cnt);
    cudaGetSymbolAddress((void**)&dis,    g_dis);
    cudaGetSymbolAddress((void**)&rowptr, g_rowptr);
    cudaGetSymbolAddress((void**)&bsum,   g_bsum);
    cudaGetSymbolAddress((void**)&csrc,   g_csrc);
    cudaGetSymbolAddress((void**)&cnrm,   g_cnrm);
    cudaGetSymbolAddress((void**)&B0,     g_B0);
    cudaGetSymbolAddress((void**)&B1,     g_B1);
    cudaGetSymbolAddress((void**)&B2,     g_B2);

    cudaFuncSetAttribute(k_gemm_dual, cudaFuncAttributeMaxDynamicSharedMemorySize, SM_BYTES);

    const int T = 256;
    int nb_n = (n + T - 1) / T;
    int nb_E = (E + T - 1) / T;
    int nb_scan = (n + 1023) / 1024;

    int ntiles = (n + 127) >> 7;                       // 391
    int S = (ntiles >= 296) ? 148 : ntiles / 3;        // H-role tile count
    int gather_blocks = (n * 32 + T - 1) / T;

    // ---- launch order arranged so the layer-0 GEMM is the 4th kernel (ncu slot)
    k_zero<<<nb_n, T>>>(cnt, n);                                        // 1
    k_hist<<<nb_E, T>>>(dst, cnt, E);                                   // 2
    k_scan_a<<<nb_scan, T>>>(cnt, rowptr, bsum, dis, n);                // 3 (+dis)
    k_gemm_dual<<<296, T, SM_BYTES>>>(x, Ws, (float*)B0, n, ntiles, S); // 4 <- profiled
    k_scan_b<<<1, 32>>>(bsum, nb_scan);                                 // 5
    k_scan_c<<<nb_n, T>>>(rowptr, bsum, n, E);                          // 6
    k_zero<<<nb_n, T>>>(cnt, n);                                        // 7
    k_fill<<<nb_E, T>>>(src, dst, dis, rowptr, cnt, csrc, cnrm, E);     // 8

    // layer 0 gather
    k_gather<<<gather_blocks, T>>>(rowptr, csrc, cnrm, dis, B0,
                                   (const float4*)(bs), B1, n);
    // layer 1
    k_gemm_dual<<<296, T, SM_BYTES>>>((const float*)B1, Ws + (size_t)H * H,
                                      (float*)B0, n, ntiles, S);
    k_gather<<<gather_blocks, T>>>(rowptr, csrc, cnrm, dis, B0,
                                   (const float4*)(bs + H), B2, n);
    // layer 2 (+ fused final projection)
    k_gemm_dual<<<296, T, SM_BYTES>>>((const float*)B2, Ws + (size_t)2 * H * H,
                                      (float*)B0, n, ntiles, S);
    k_gather_final<<<gather_blocks, T>>>(rowptr, csrc, cnrm, dis, B0,
                                         (const float4*)(bs + 2 * H),
                                         (const float4*)Wl, bl, (float*)d_out, n);
}

// round 14
// speedup vs baseline: 1.5429x; 1.3023x over previous
#include <cuda_runtime.h>
#include <cuda_bf16.h>
#include <math.h>
#include <stdint.h>

#define NMAX 50000
#define EMAX 800000
#define H 128

// Scratch (device globals — no allocation anywhere)
__device__ int    g_cnt[NMAX];
__device__ float  g_dis[NMAX];
__device__ int    g_rowptr[NMAX + 1];
__device__ int    g_bsum[64];
__device__ int    g_csrc[EMAX];
__device__ float  g_cnrm[EMAX];
__device__ float4 g_B0[NMAX * 32];
__device__ float4 g_B1[NMAX * 32];
__device__ float4 g_B2[NMAX * 32];

// ===========================================================================
// bf16x3 mma.sync GEMM with ldmatrix fragments
//   C[M x 128] = A[M x 128] @ W[128 x 128]
//   A = Ahi+Alo, W = Whi+Wlo;  D = AhiWhi + AloWhi + AhiWlo
// 256 thr, 2 CTAs/SM, W (hi/lo) resident in SMEM; A staged in k16 chunks x2 buf
// ===========================================================================
#define WS_OFF   0
#define W_TERM   34816     // [128 n][136 k] bf16, row stride 272 B
#define AS_OFF   69632     // 2 buf x 2 term x [128 m][24 k] bf16, row stride 48 B
#define AS_BT    6144
#define SM_BYTES 94208

__device__ __forceinline__ void mma_bf16(float4& d, const uint32_t* a,
                                         uint32_t b0, uint32_t b1) {
    asm volatile(
        "mma.sync.aligned.m16n8k16.row.col.f32.bf16.bf16.f32 "
        "{%0,%1,%2,%3}, {%4,%5,%6,%7}, {%8,%9}, {%0,%1,%2,%3};\n"
        : "+f"(d.x), "+f"(d.y), "+f"(d.z), "+f"(d.w)
        : "r"(a[0]), "r"(a[1]), "r"(a[2]), "r"(a[3]), "r"(b0), "r"(b1));
}

__device__ __forceinline__ void ldsm_x4(uint32_t* r, uint32_t addr) {
    asm volatile(
        "ldmatrix.sync.aligned.m8n8.x4.shared.b16 {%0,%1,%2,%3}, [%4];"
        : "=r"(r[0]), "=r"(r[1]), "=r"(r[2]), "=r"(r[3]) : "r"(addr));
}

__device__ __forceinline__ void split4(float4 v, uint2& h, uint2& l) {
    __nv_bfloat162 hxy = __floats2bfloat162_rn(v.x, v.y);
    __nv_bfloat162 hzw = __floats2bfloat162_rn(v.z, v.w);
    float2 fxy = __bfloat1622float2(hxy);
    float2 fzw = __bfloat1622float2(hzw);
    __nv_bfloat162 lxy = __floats2bfloat162_rn(v.x - fxy.x, v.y - fxy.y);
    __nv_bfloat162 lzw = __floats2bfloat162_rn(v.z - fzw.x, v.w - fzw.y);
    h.x = *(uint32_t*)&hxy; h.y = *(uint32_t*)&hzw;
    l.x = *(uint32_t*)&lxy; l.y = *(uint32_t*)&lzw;
}

__global__ __launch_bounds__(256, 2) void k_gemm_h(
    const float* __restrict__ A, const float* __restrict__ W,
    float* __restrict__ C, int M, int ntiles)
{
    extern __shared__ char sm[];
    const int tid  = threadIdx.x;
    const int lane = tid & 31;
    const int wid  = tid >> 5;
    const int wm   = wid & 3;       // 4 x 32 rows
    const int wn   = wid >> 2;      // 2 x 64 cols
    const int g    = lane >> 2;
    const int tg   = lane & 3;

    // ---- W -> bf16 hi/lo in SMEM (once per CTA). W[k][n] stored as Wsm[n][k].
    for (int idx = tid; idx < 128 * 128; idx += 256) {
        int k = idx >> 7, n = idx & 127;
        float w = __ldg(W + idx);
        __nv_bfloat16 hb = __float2bfloat16_rn(w);
        __nv_bfloat16 lb = __float2bfloat16_rn(w - __bfloat162float(hb));
        *(__nv_bfloat16*)(sm + WS_OFF + (size_t)n * 272 + k * 2)          = hb;
        *(__nv_bfloat16*)(sm + WS_OFF + W_TERM + (size_t)n * 272 + k * 2) = lb;
    }
    __syncthreads();

    const uint32_t smb = (uint32_t)__cvta_generic_to_shared(sm);

    // ldmatrix lane addressing:
    //  A x4: lanes 0-7 rows m..m+7 (k 0-7), 8-15 rows m+8..15, 16-23 rows m..7 k+8, 24-31 rows m+8..15 k+8
    const int aRow = wm * 32 + (lane & 15);
    const uint32_t aBase = smb + AS_OFF + (uint32_t)aRow * 48 + ((lane >> 4) << 4);
    //  B x4: matrices = [n..n+7,k0-7], [n..n+7,k8-15], [n+8..15,k0-7], [n+8..15,k8-15]
    const int bRow = wn * 64 + (lane & 7) + ((lane >> 4) << 3);
    const uint32_t bBase = smb + WS_OFF + (uint32_t)bRow * 272 + (((lane >> 3) & 1) << 4);

    const int srow = tid >> 1;
    const int sk   = (tid & 1) * 8;

    for (int t = blockIdx.x; t < ntiles; t += gridDim.x) {
        const int m0 = t << 7;

        float4 c[2][8];
#pragma unroll
        for (int mt = 0; mt < 2; mt++)
#pragma unroll
            for (int nt = 0; nt < 8; nt++) c[mt][nt] = make_float4(0.f, 0.f, 0.f, 0.f);

        const int  grow = m0 + srow;
        const bool rok  = grow < M;
        const float* ap = A + (size_t)grow * H + sk;
        const float4 z4 = make_float4(0.f, 0.f, 0.f, 0.f);

        float4 s0 = rok ? *(const float4*)(ap)     : z4;
        float4 s1 = rok ? *(const float4*)(ap + 4) : z4;
        {
            uint2 h, l;
            char* b = sm + AS_OFF + (size_t)srow * 48 + sk * 2;
            split4(s0, h, l);
            *(uint2*)(b)     = h;  *(uint2*)(b + AS_BT)     = l;
            split4(s1, h, l);
            *(uint2*)(b + 8) = h;  *(uint2*)(b + AS_BT + 8) = l;
        }

#pragma unroll
        for (int kc = 0; kc < 8; kc++) {
            if (kc < 7) {
                const float* p = ap + (kc + 1) * 16;
                s0 = rok ? *(const float4*)(p)     : z4;
                s1 = rok ? *(const float4*)(p + 4) : z4;
            }
            __syncthreads();
            const int buf = kc & 1;
            const uint32_t ab = aBase + (uint32_t)(buf * 2) * AS_BT;
            const uint32_t bk = bBase + (uint32_t)kc * 32;

            // A fragments via ldmatrix (hi and lo)
            uint32_t ah[2][4], al[2][4];
            ldsm_x4(ah[0], ab);
            ldsm_x4(ah[1], ab + 16 * 48);
            ldsm_x4(al[0], ab + AS_BT);
            ldsm_x4(al[1], ab + AS_BT + 16 * 48);

            // B hi fragments: 4 x ldmatrix.x4 covers all 8 n-tiles (b0,b1 each)
            uint32_t bb[4][4];
#pragma unroll
            for (int np = 0; np < 4; np++)
                ldsm_x4(bb[np], bk + (uint32_t)np * 16 * 272);

            // phase 1+2: (Ahi + Alo) x Bhi
#pragma unroll
            for (int nt = 0; nt < 8; nt++) {
                uint32_t b0 = bb[nt >> 1][(nt & 1) * 2];
                uint32_t b1 = bb[nt >> 1][(nt & 1) * 2 + 1];
                mma_bf16(c[0][nt], ah[0], b0, b1);
                mma_bf16(c[1][nt], ah[1], b0, b1);
                mma_bf16(c[0][nt], al[0], b0, b1);
                mma_bf16(c[1][nt], al[1], b0, b1);
            }

            // B lo fragments (reuse regs)
#pragma unroll
            for (int np = 0; np < 4; np++)
                ldsm_x4(bb[np], bk + W_TERM + (uint32_t)np * 16 * 272);

            // phase 3: Ahi x Blo
#pragma unroll
            for (int nt = 0; nt < 8; nt++) {
                uint32_t b0 = bb[nt >> 1][(nt & 1) * 2];
                uint32_t b1 = bb[nt >> 1][(nt & 1) * 2 + 1];
                mma_bf16(c[0][nt], ah[0], b0, b1);
                mma_bf16(c[1][nt], ah[1], b0, b1);
            }

            if (kc < 7) {
                uint2 h, l;
                char* b = sm + AS_OFF + (size_t)(((kc + 1) & 1) * 2) * AS_BT
                        + (size_t)srow * 48 + sk * 2;
                split4(s0, h, l);
                *(uint2*)(b)     = h;  *(uint2*)(b + AS_BT)     = l;
                split4(s1, h, l);
                *(uint2*)(b + 8) = h;  *(uint2*)(b + AS_BT + 8) = l;
            }
        }

        // epilogue
#pragma unroll
        for (int mt = 0; mt < 2; mt++) {
            int r0 = m0 + wm * 32 + mt * 16 + g;
#pragma unroll
            for (int nt = 0; nt < 8; nt++) {
                int col = wn * 64 + nt * 8 + tg * 2;
                float4 v = c[mt][nt];
                if (r0 < M)     *(float2*)(C + (size_t)r0 * H + col)       = make_float2(v.x, v.y);
                if (r0 + 8 < M) *(float2*)(C + (size_t)(r0 + 8) * H + col) = make_float2(v.z, v.w);
            }
        }
    }
}

// ===========================================================================
// CSR build
// ===========================================================================
__global__ void k_zero(int* __restrict__ p, int n) {
    int i = blockIdx.x * blockDim.x + threadIdx.x;
    if (i < n) p[i] = 0;
}
__global__ void k_hist(const int* __restrict__ dst, int* __restrict__ cnt, int E) {
    int i = blockIdx.x * blockDim.x + threadIdx.x;
    if (i < E) atomicAdd(&cnt[dst[i]], 1);
}
// exclusive scan + dis = rsqrt(cnt+1) fused
__global__ void k_scan_a(const int* __restrict__ cnt, int* __restrict__ out,
                         int* __restrict__ bsum, float* __restrict__ dis, int n) {
    __shared__ int sh[256];
    int tid = threadIdx.x;
    int idx0 = blockIdx.x * 1024 + tid * 4;
    int it[4];
#pragma unroll
    for (int i = 0; i < 4; i++) {
        it[i] = (idx0 + i < n) ? cnt[idx0 + i] : 0;
        if (idx0 + i < n) dis[idx0 + i] = rsqrtf((float)(it[i] + 1));
    }
    int sum = it[0] + it[1] + it[2] + it[3];
    sh[tid] = sum;
    __syncthreads();
#pragma unroll
    for (int off = 1; off < 256; off <<= 1) {
        int v = (tid >= off) ? sh[tid - off] : 0;
        __syncthreads();
        sh[tid] += v;
        __syncthreads();
    }
    int run = sh[tid] - sum;
#pragma unroll
    for (int i = 0; i < 4; i++) {
        if (idx0 + i < n) out[idx0 + i] = run;
        run += it[i];
    }
    if (tid == 255) bsum[blockIdx.x] = sh[255];
}
__global__ void k_scan_b(int* __restrict__ bsum, int nb) {
    if (threadIdx.x == 0) {
        int acc = 0;
        for (int i = 0; i < nb; i++) { int v = bsum[i]; bsum[i] = acc; acc += v; }
    }
}
__global__ void k_scan_c(int* __restrict__ out, const int* __restrict__ bsum, int n, int E) {
    int i = blockIdx.x * blockDim.x + threadIdx.x;
    if (i < n) out[i] += bsum[i >> 10];
    if (i == 0) out[n] = E;
}
__global__ void k_fill(const int* __restrict__ src, const int* __restrict__ dst,
                       const float* __restrict__ dis, const int* __restrict__ rowptr,
                       int* __restrict__ fill, int* __restrict__ csrc,
                       float* __restrict__ cnrm, int E) {
    int e = blockIdx.x * blockDim.x + threadIdx.x;
    if (e >= E) return;
    int s = src[e], d = dst[e];
    int pos = rowptr[d] + atomicAdd(&fill[d], 1);
    csrc[pos] = s;
    cnrm[pos] = dis[s] * dis[d];
}

// ===========================================================================
// Fused gather + self-loop + bias + ELU (warp per node)
// ===========================================================================
__device__ __forceinline__ float4 gather_acc(
    const int* __restrict__ rowptr, const int* __restrict__ csrc,
    const float* __restrict__ cnrm, const float* __restrict__ dis,
    const float4* __restrict__ h2, const float4* __restrict__ b4,
    int v, int lane)
{
    float s = dis[v];
    float selfw = s * s;
    float4 acc = __ldg(h2 + (size_t)v * 32 + lane);
    acc.x *= selfw; acc.y *= selfw; acc.z *= selfw; acc.w *= selfw;

    int j   = __ldg(rowptr + v);
    int end = __ldg(rowptr + v + 1);

    for (; j + 1 < end; j += 2) {
        int   s0 = __ldg(csrc + j),     s1 = __ldg(csrc + j + 1);
        float w0 = __ldg(cnrm + j),     w1 = __ldg(cnrm + j + 1);
        float4 t0 = __ldg(h2 + (size_t)s0 * 32 + lane);
        float4 t1 = __ldg(h2 + (size_t)s1 * 32 + lane);
        acc.x = fmaf(t0.x, w0, acc.x); acc.x = fmaf(t1.x, w1, acc.x);
        acc.y = fmaf(t0.y, w0, acc.y); acc.y = fmaf(t1.y, w1, acc.y);
        acc.z = fmaf(t0.z, w0, acc.z); acc.z = fmaf(t1.z, w1, acc.z);
        acc.w = fmaf(t0.w, w0, acc.w); acc.w = fmaf(t1.w, w1, acc.w);
    }
    if (j < end) {
        int   s0 = __ldg(csrc + j);
        float w0 = __ldg(cnrm + j);
        float4 t0 = __ldg(h2 + (size_t)s0 * 32 + lane);
        acc.x = fmaf(t0.x, w0, acc.x);
        acc.y = fmaf(t0.y, w0, acc.y);
        acc.z = fmaf(t0.z, w0, acc.z);
        acc.w = fmaf(t0.w, w0, acc.w);
    }

    float4 b = __ldg(b4 + lane);
    acc.x += b.x; acc.y += b.y; acc.z += b.z; acc.w += b.w;
    acc.x = acc.x > 0.f ? acc.x : expm1f(acc.x);
    acc.y = acc.y > 0.f ? acc.y : expm1f(acc.y);
    acc.z = acc.z > 0.f ? acc.z : expm1f(acc.z);
    acc.w = acc.w > 0.f ? acc.w : expm1f(acc.w);
    return acc;
}

__global__ __launch_bounds__(256) void k_gather(
    const int* __restrict__ rowptr, const int* __restrict__ csrc,
    const float* __restrict__ cnrm, const float* __restrict__ dis,
    const float4* __restrict__ h2, const float4* __restrict__ b4,
    float4* __restrict__ out, int n)
{
    int gt   = blockIdx.x * blockDim.x + threadIdx.x;
    int v    = gt >> 5;
    int lane = threadIdx.x & 31;
    if (v >= n) return;
    out[(size_t)v * 32 + lane] =
        gather_acc(rowptr, csrc, cnrm, dis, h2, b4, v, lane);
}

// last layer: gather + bias + ELU + dot(Wl) + bl
__global__ __launch_bounds__(256) void k_gather_final(
    const int* __restrict__ rowptr, const int* __restrict__ csrc,
    const float* __restrict__ cnrm, const float* __restrict__ dis,
    const float4* __restrict__ h2, const float4* __restrict__ b4,
    const float4* __restrict__ Wl4, const float* __restrict__ bl,
    float* __restrict__ out, int n)
{
    int gt   = blockIdx.x * blockDim.x + threadIdx.x;
    int v    = gt >> 5;
    int lane = threadIdx.x & 31;
    if (v >= n) return;
    float4 acc = gather_acc(rowptr, csrc, cnrm, dis, h2, b4, v, lane);
    float4 wv  = __ldg(Wl4 + lane);
    float p = acc.x * wv.x + acc.y * wv.y + acc.z * wv.z + acc.w * wv.w;
#pragma unroll
    for (int o = 16; o > 0; o >>= 1) p += __shfl_xor_sync(0xffffffff, p, o);
    if (lane == 0) out[v] = p + __ldg(bl);
}

// ===========================================================================
extern "C" void kernel_launch(void* const* d_in, const int* in_sizes, int n_in,
                              void* d_out, int out_size) {
    const float* x  = (const float*)d_in[0];
    const float* Ws = (const float*)d_in[1];
    const float* bs = (const float*)d_in[2];
    const float* Wl = (const float*)d_in[3];
    const float* bl = (const float*)d_in[4];
    const int*   ei = (const int*)d_in[5];

    int n = in_sizes[0] / H;      // 50000
    int E = in_sizes[5] / 2;      // 800000
    const int* src = ei;
    const int* dst = ei + E;

    int *cnt, *rowptr, *bsum, *csrc;
    float *dis, *cnrm;
    float4 *B0, *B1, *B2;
    cudaGetSymbolAddress((void**)&cnt,    g_cnt);
    cudaGetSymbolAddress((void**)&dis,    g_dis);
    cudaGetSymbolAddress((void**)&rowptr, g_rowptr);
    cudaGetSymbolAddress((void**)&bsum,   g_bsum);
    cudaGetSymbolAddress((void**)&csrc,   g_csrc);
    cudaGetSymbolAddress((void**)&cnrm,   g_cnrm);
    cudaGetSymbolAddress((void**)&B0,     g_B0);
    cudaGetSymbolAddress((void**)&B1,     g_B1);
    cudaGetSymbolAddress((void**)&B2,     g_B2);

    cudaFuncSetAttribute(k_gemm_h, cudaFuncAttributeMaxDynamicSharedMemorySize, SM_BYTES);

    const int T = 256;
    int nb_n = (n + T - 1) / T;
    int nb_E = (E + T - 1) / T;
    int nb_scan = (n + 1023) / 1024;

    int ntiles = (n + 127) >> 7;                  // 391
    int gather_blocks = (n * 32 + T - 1) / T;

    // ---- layer-0 GEMM placed 4th so ncu (-s 5 -c 1 skips 3) profiles it
    k_zero<<<nb_n, T>>>(cnt, n);                                        // 1
    k_hist<<<nb_E, T>>>(dst, cnt, E);                                   // 2
    k_scan_a<<<nb_scan, T>>>(cnt, rowptr, bsum, dis, n);                // 3
    k_gemm_h<<<296, T, SM_BYTES>>>(x, Ws, (float*)B0, n, ntiles);       // 4 <- profiled
    k_scan_b<<<1, 32>>>(bsum, nb_scan);                                 // 5
    k_scan_c<<<nb_n, T>>>(rowptr, bsum, n, E);                          // 6
    k_zero<<<nb_n, T>>>(cnt, n);                                        // 7
    k_fill<<<nb_E, T>>>(src, dst, dis, rowptr, cnt, csrc, cnrm, E);     // 8

    // layer 0 gather
    k_gather<<<gather_blocks, T>>>(rowptr, csrc, cnrm, dis, B0,
                                   (const float4*)(bs), B1, n);
    // layer 1
    k_gemm_h<<<296, T, SM_BYTES>>>((const float*)B1, Ws + (size_t)H * H,
                                   (float*)B0, n, ntiles);
    k_gather<<<gather_blocks, T>>>(rowptr, csrc, cnrm, dis, B0,
                                   (const float4*)(bs + H), B2, n);
    // layer 2 (+ fused final projection)
    k_gemm_h<<<296, T, SM_BYTES>>>((const float*)B2, Ws + (size_t)2 * H * H,
                                   (float*)B0, n, ntiles);
    k_gather_final<<<gather_blocks, T>>>(rowptr, csrc, cnrm, dis, B0,
                                         (const float4*)(bs + 2 * H),
                                         (const float4*)Wl, bl, (float*)d_out, n);
}

// round 15
// speedup vs baseline: 1.5903x; 1.0307x over previous
#include <cuda_runtime.h>
#include <cuda_bf16.h>
#include <math.h>
#include <stdint.h>

#define NMAX 50000
#define EMAX 800000
#define H 128

// Scratch (device globals — no allocation anywhere)
__device__ int    g_cnt[NMAX];
__device__ float  g_dis[NMAX];
__device__ int    g_rowptr[NMAX + 1];
__device__ int    g_bsum[64];
__device__ int    g_csrc[EMAX];
__device__ float  g_cnrm[EMAX];
__device__ float4 g_B0[NMAX * 32];
__device__ float4 g_B1[NMAX * 32];
__device__ float4 g_B2[NMAX * 32];

// ===========================================================================
// bf16x3 mma.sync GEMM with ldmatrix fragments (unchanged from R14 win)
// ===========================================================================
#define WS_OFF   0
#define W_TERM   34816
#define AS_OFF   69632
#define AS_BT    6144
#define SM_BYTES 94208

__device__ __forceinline__ void mma_bf16(float4& d, const uint32_t* a,
                                         uint32_t b0, uint32_t b1) {
    asm volatile(
        "mma.sync.aligned.m16n8k16.row.col.f32.bf16.bf16.f32 "
        "{%0,%1,%2,%3}, {%4,%5,%6,%7}, {%8,%9}, {%0,%1,%2,%3};\n"
        : "+f"(d.x), "+f"(d.y), "+f"(d.z), "+f"(d.w)
        : "r"(a[0]), "r"(a[1]), "r"(a[2]), "r"(a[3]), "r"(b0), "r"(b1));
}

__device__ __forceinline__ void ldsm_x4(uint32_t* r, uint32_t addr) {
    asm volatile(
        "ldmatrix.sync.aligned.m8n8.x4.shared.b16 {%0,%1,%2,%3}, [%4];"
        : "=r"(r[0]), "=r"(r[1]), "=r"(r[2]), "=r"(r[3]) : "r"(addr));
}

__device__ __forceinline__ void split4(float4 v, uint2& h, uint2& l) {
    __nv_bfloat162 hxy = __floats2bfloat162_rn(v.x, v.y);
    __nv_bfloat162 hzw = __floats2bfloat162_rn(v.z, v.w);
    float2 fxy = __bfloat1622float2(hxy);
    float2 fzw = __bfloat1622float2(hzw);
    __nv_bfloat162 lxy = __floats2bfloat162_rn(v.x - fxy.x, v.y - fxy.y);
    __nv_bfloat162 lzw = __floats2bfloat162_rn(v.z - fzw.x, v.w - fzw.y);
    h.x = *(uint32_t*)&hxy; h.y = *(uint32_t*)&hzw;
    l.x = *(uint32_t*)&lxy; l.y = *(uint32_t*)&lzw;
}

__global__ __launch_bounds__(256, 2) void k_gemm_h(
    const float* __restrict__ A, const float* __restrict__ W,
    float* __restrict__ C, int M, int ntiles)
{
    extern __shared__ char sm[];
    const int tid  = threadIdx.x;
    const int lane = tid & 31;
    const int wid  = tid >> 5;
    const int wm   = wid & 3;
    const int wn   = wid >> 2;
    const int g    = lane >> 2;
    const int tg   = lane & 3;

    for (int idx = tid; idx < 128 * 128; idx += 256) {
        int k = idx >> 7, n = idx & 127;
        float w = __ldg(W + idx);
        __nv_bfloat16 hb = __float2bfloat16_rn(w);
        __nv_bfloat16 lb = __float2bfloat16_rn(w - __bfloat162float(hb));
        *(__nv_bfloat16*)(sm + WS_OFF + (size_t)n * 272 + k * 2)          = hb;
        *(__nv_bfloat16*)(sm + WS_OFF + W_TERM + (size_t)n * 272 + k * 2) = lb;
    }
    __syncthreads();

    const uint32_t smb = (uint32_t)__cvta_generic_to_shared(sm);
    const int aRow = wm * 32 + (lane & 15);
    const uint32_t aBase = smb + AS_OFF + (uint32_t)aRow * 48 + ((lane >> 4) << 4);
    const int bRow = wn * 64 + (lane & 7) + ((lane >> 4) << 3);
    const uint32_t bBase = smb + WS_OFF + (uint32_t)bRow * 272 + (((lane >> 3) & 1) << 4);

    const int srow = tid >> 1;
    const int sk   = (tid & 1) * 8;

    for (int t = blockIdx.x; t < ntiles; t += gridDim.x) {
        const int m0 = t << 7;

        float4 c[2][8];
#pragma unroll
        for (int mt = 0; mt < 2; mt++)
#pragma unroll
            for (int nt = 0; nt < 8; nt++) c[mt][nt] = make_float4(0.f, 0.f, 0.f, 0.f);

        const int  grow = m0 + srow;
        const bool rok  = grow < M;
        const float* ap = A + (size_t)grow * H + sk;
        const float4 z4 = make_float4(0.f, 0.f, 0.f, 0.f);

        float4 s0 = rok ? *(const float4*)(ap)     : z4;
        float4 s1 = rok ? *(const float4*)(ap + 4) : z4;
        {
            uint2 h, l;
            char* b = sm + AS_OFF + (size_t)srow * 48 + sk * 2;
            split4(s0, h, l);
            *(uint2*)(b)     = h;  *(uint2*)(b + AS_BT)     = l;
            split4(s1, h, l);
            *(uint2*)(b + 8) = h;  *(uint2*)(b + AS_BT + 8) = l;
        }

#pragma unroll
        for (int kc = 0; kc < 8; kc++) {
            if (kc < 7) {
                const float* p = ap + (kc + 1) * 16;
                s0 = rok ? *(const float4*)(p)     : z4;
                s1 = rok ? *(const float4*)(p + 4) : z4;
            }
            __syncthreads();
            const int buf = kc & 1;
            const uint32_t ab = aBase + (uint32_t)(buf * 2) * AS_BT;
            const uint32_t bk = bBase + (uint32_t)kc * 32;

            uint32_t ah[2][4], al[2][4];
            ldsm_x4(ah[0], ab);
            ldsm_x4(ah[1], ab + 16 * 48);
            ldsm_x4(al[0], ab + AS_BT);
            ldsm_x4(al[1], ab + AS_BT + 16 * 48);

            uint32_t bb[4][4];
#pragma unroll
            for (int np = 0; np < 4; np++)
                ldsm_x4(bb[np], bk + (uint32_t)np * 16 * 272);

#pragma unroll
            for (int nt = 0; nt < 8; nt++) {
                uint32_t b0 = bb[nt >> 1][(nt & 1) * 2];
                uint32_t b1 = bb[nt >> 1][(nt & 1) * 2 + 1];
                mma_bf16(c[0][nt], ah[0], b0, b1);
                mma_bf16(c[1][nt], ah[1], b0, b1);
                mma_bf16(c[0][nt], al[0], b0, b1);
                mma_bf16(c[1][nt], al[1], b0, b1);
            }

#pragma unroll
            for (int np = 0; np < 4; np++)
                ldsm_x4(bb[np], bk + W_TERM + (uint32_t)np * 16 * 272);

#pragma unroll
            for (int nt = 0; nt < 8; nt++) {
                uint32_t b0 = bb[nt >> 1][(nt & 1) * 2];
                uint32_t b1 = bb[nt >> 1][(nt & 1) * 2 + 1];
                mma_bf16(c[0][nt], ah[0], b0, b1);
                mma_bf16(c[1][nt], ah[1], b0, b1);
            }

            if (kc < 7) {
                uint2 h, l;
                char* b = sm + AS_OFF + (size_t)(((kc + 1) & 1) * 2) * AS_BT
                        + (size_t)srow * 48 + sk * 2;
                split4(s0, h, l);
                *(uint2*)(b)     = h;  *(uint2*)(b + AS_BT)     = l;
                split4(s1, h, l);
                *(uint2*)(b + 8) = h;  *(uint2*)(b + AS_BT + 8) = l;
            }
        }

#pragma unroll
        for (int mt = 0; mt < 2; mt++) {
            int r0 = m0 + wm * 32 + mt * 16 + g;
#pragma unroll
            for (int nt = 0; nt < 8; nt++) {
                int col = wn * 64 + nt * 8 + tg * 2;
                float4 v = c[mt][nt];
                if (r0 < M)     *(float2*)(C + (size_t)r0 * H + col)       = make_float2(v.x, v.y);
                if (r0 + 8 < M) *(float2*)(C + (size_t)(r0 + 8) * H + col) = make_float2(v.z, v.w);
            }
        }
    }
}

// ===========================================================================
// CSR build
// ===========================================================================
__global__ void k_zero(int* __restrict__ p, int n) {
    int i = blockIdx.x * blockDim.x + threadIdx.x;
    if (i < n) p[i] = 0;
}
__global__ void k_hist(const int* __restrict__ dst, int* __restrict__ cnt, int E) {
    int i = blockIdx.x * blockDim.x + threadIdx.x;
    if (i < E) atomicAdd(&cnt[dst[i]], 1);
}
__global__ void k_scan_a(const int* __restrict__ cnt, int* __restrict__ out,
                         int* __restrict__ bsum, float* __restrict__ dis, int n) {
    __shared__ int sh[256];
    int tid = threadIdx.x;
    int idx0 = blockIdx.x * 1024 + tid * 4;
    int it[4];
#pragma unroll
    for (int i = 0; i < 4; i++) {
        it[i] = (idx0 + i < n) ? cnt[idx0 + i] : 0;
        if (idx0 + i < n) dis[idx0 + i] = rsqrtf((float)(it[i] + 1));
    }
    int sum = it[0] + it[1] + it[2] + it[3];
    sh[tid] = sum;
    __syncthreads();
#pragma unroll
    for (int off = 1; off < 256; off <<= 1) {
        int v = (tid >= off) ? sh[tid - off] : 0;
        __syncthreads();
        sh[tid] += v;
        __syncthreads();
    }
    int run = sh[tid] - sum;
#pragma unroll
    for (int i = 0; i < 4; i++) {
        if (idx0 + i < n) out[idx0 + i] = run;
        run += it[i];
    }
    if (tid == 255) bsum[blockIdx.x] = sh[255];
}
__global__ void k_scan_b(int* __restrict__ bsum, int nb) {
    if (threadIdx.x == 0) {
        int acc = 0;
        for (int i = 0; i < nb; i++) { int v = bsum[i]; bsum[i] = acc; acc += v; }
    }
}
__global__ void k_scan_c(int* __restrict__ out, const int* __restrict__ bsum, int n, int E) {
    int i = blockIdx.x * blockDim.x + threadIdx.x;
    if (i < n) out[i] += bsum[i >> 10];
    if (i == 0) out[n] = E;
}
__global__ void k_fill(const int* __restrict__ src, const int* __restrict__ dst,
                       const float* __restrict__ dis, const int* __restrict__ rowptr,
                       int* __restrict__ fill, int* __restrict__ csrc,
                       float* __restrict__ cnrm, int E) {
    int e = blockIdx.x * blockDim.x + threadIdx.x;
    if (e >= E) return;
    int s = src[e], d = dst[e];
    int pos = rowptr[d] + atomicAdd(&fill[d], 1);
    csrc[pos] = s;
    cnrm[pos] = dis[s] * dis[d];
}

// ===========================================================================
// Fused gather + self-loop + bias + ELU (warp per node), edge loop unrolled x4
// ===========================================================================
__device__ __forceinline__ float4 gather_acc(
    const int* __restrict__ rowptr, const int* __restrict__ csrc,
    const float* __restrict__ cnrm, const float* __restrict__ dis,
    const float4* __restrict__ h2, const float4* __restrict__ b4,
    int v, int lane)
{
    float s = dis[v];
    float selfw = s * s;
    float4 acc = __ldg(h2 + (size_t)v * 32 + lane);
    acc.x *= selfw; acc.y *= selfw; acc.z *= selfw; acc.w *= selfw;

    int j   = __ldg(rowptr + v);
    int end = __ldg(rowptr + v + 1);

    for (; j + 3 < end; j += 4) {
        int   s0 = __ldg(csrc + j),     s1 = __ldg(csrc + j + 1);
        int   s2 = __ldg(csrc + j + 2), s3 = __ldg(csrc + j + 3);
        float w0 = __ldg(cnrm + j),     w1 = __ldg(cnrm + j + 1);
        float w2 = __ldg(cnrm + j + 2), w3 = __ldg(cnrm + j + 3);
        float4 t0 = __ldg(h2 + (size_t)s0 * 32 + lane);
        float4 t1 = __ldg(h2 + (size_t)s1 * 32 + lane);
        float4 t2 = __ldg(h2 + (size_t)s2 * 32 + lane);
        float4 t3 = __ldg(h2 + (size_t)s3 * 32 + lane);
        acc.x = fmaf(t0.x, w0, acc.x); acc.y = fmaf(t0.y, w0, acc.y);
        acc.z = fmaf(t0.z, w0, acc.z); acc.w = fmaf(t0.w, w0, acc.w);
        acc.x = fmaf(t1.x, w1, acc.x); acc.y = fmaf(t1.y, w1, acc.y);
        acc.z = fmaf(t1.z, w1, acc.z); acc.w = fmaf(t1.w, w1, acc.w);
        acc.x = fmaf(t2.x, w2, acc.x); acc.y = fmaf(t2.y, w2, acc.y);
        acc.z = fmaf(t2.z, w2, acc.z); acc.w = fmaf(t2.w, w2, acc.w);
        acc.x = fmaf(t3.x, w3, acc.x); acc.y = fmaf(t3.y, w3, acc.y);
        acc.z = fmaf(t3.z, w3, acc.z); acc.w = fmaf(t3.w, w3, acc.w);
    }
    for (; j < end; j++) {
        int   s0 = __ldg(csrc + j);
        float w0 = __ldg(cnrm + j);
        float4 t0 = __ldg(h2 + (size_t)s0 * 32 + lane);
        acc.x = fmaf(t0.x, w0, acc.x);
        acc.y = fmaf(t0.y, w0, acc.y);
        acc.z = fmaf(t0.z, w0, acc.z);
        acc.w = fmaf(t0.w, w0, acc.w);
    }

    float4 b = __ldg(b4 + lane);
    acc.x += b.x; acc.y += b.y; acc.z += b.z; acc.w += b.w;
    acc.x = acc.x > 0.f ? acc.x : expm1f(acc.x);
    acc.y = acc.y > 0.f ? acc.y : expm1f(acc.y);
    acc.z = acc.z > 0.f ? acc.z : expm1f(acc.z);
    acc.w = acc.w > 0.f ? acc.w : expm1f(acc.w);
    return acc;
}

__global__ __launch_bounds__(256) void k_gather(
    const int* __restrict__ rowptr, const int* __restrict__ csrc,
    const float* __restrict__ cnrm, const float* __restrict__ dis,
    const float4* __restrict__ h2, const float4* __restrict__ b4,
    float4* __restrict__ out, int n)
{
    int gt   = blockIdx.x * blockDim.x + threadIdx.x;
    int v    = gt >> 5;
    int lane = threadIdx.x & 31;
    if (v >= n) return;
    out[(size_t)v * 32 + lane] =
        gather_acc(rowptr, csrc, cnrm, dis, h2, b4, v, lane);
}

__global__ __launch_bounds__(256) void k_gather_final(
    const int* __restrict__ rowptr, const int* __restrict__ csrc,
    const float* __restrict__ cnrm, const float* __restrict__ dis,
    const float4* __restrict__ h2, const float4* __restrict__ b4,
    const float4* __restrict__ Wl4, const float* __restrict__ bl,
    float* __restrict__ out, int n)
{
    int gt   = blockIdx.x * blockDim.x + threadIdx.x;
    int v    = gt >> 5;
    int lane = threadIdx.x & 31;
    if (v >= n) return;
    float4 acc = gather_acc(rowptr, csrc, cnrm, dis, h2, b4, v, lane);
    float4 wv  = __ldg(Wl4 + lane);
    float p = acc.x * wv.x + acc.y * wv.y + acc.z * wv.z + acc.w * wv.w;
#pragma unroll
    for (int o = 16; o > 0; o >>= 1) p += __shfl_xor_sync(0xffffffff, p, o);
    if (lane == 0) out[v] = p + __ldg(bl);
}

// ===========================================================================
extern "C" void kernel_launch(void* const* d_in, const int* in_sizes, int n_in,
                              void* d_out, int out_size) {
    const float* x  = (const float*)d_in[0];
    const float* Ws = (const float*)d_in[1];
    const float* bs = (const float*)d_in[2];
    const float* Wl = (const float*)d_in[3];
    const float* bl = (const float*)d_in[4];
    const int*   ei = (const int*)d_in[5];

    int n = in_sizes[0] / H;      // 50000
    int E = in_sizes[5] / 2;      // 800000
    const int* src = ei;
    const int* dst = ei + E;

    int *cnt, *rowptr, *bsum, *csrc;
    float *dis, *cnrm;
    float4 *B0, *B1, *B2;
    cudaGetSymbolAddress((void**)&cnt,    g_cnt);
    cudaGetSymbolAddress((void**)&dis,    g_dis);
    cudaGetSymbolAddress((void**)&rowptr, g_rowptr);
    cudaGetSymbolAddress((void**)&bsum,   g_bsum);
    cudaGetSymbolAddress((void**)&csrc,   g_csrc);
    cudaGetSymbolAddress((void**)&cnrm,   g_cnrm);
    cudaGetSymbolAddress((void**)&B0,     g_B0);
    cudaGetSymbolAddress((void**)&B1,     g_B1);
    cudaGetSymbolAddress((void**)&B2,     g_B2);

    cudaFuncSetAttribute(k_gemm_h, cudaFuncAttributeMaxDynamicSharedMemorySize, SM_BYTES);

    // one-time side-stream + events (host-side resources; created outside capture
    // on the first (correctness) call, reused verbatim on the capture call)
    static cudaStream_t s1 = 0;
    static cudaEvent_t evFork = 0, evJoin = 0;
    if (s1 == 0) {
        cudaStreamCreateWithFlags(&s1, cudaStreamNonBlocking);
        cudaEventCreateWithFlags(&evFork, cudaEventDisableTiming);
        cudaEventCreateWithFlags(&evJoin, cudaEventDisableTiming);
    }

    const int T = 256;
    int nb_n = (n + T - 1) / T;
    int nb_E = (E + T - 1) / T;
    int nb_scan = (n + 1023) / 1024;

    int ntiles = (n + 127) >> 7;
    int gather_blocks = (n * 32 + T - 1) / T;

    // ---- fork: CSR build on s1 runs concurrently with GEMM layer 0 on s0
    cudaEventRecord(evFork, 0);
    cudaStreamWaitEvent(s1, evFork, 0);

    k_gemm_h<<<296, T, SM_BYTES>>>(x, Ws, (float*)B0, n, ntiles);           // s0

    k_zero<<<nb_n, T, 0, s1>>>(cnt, n);                                     // s1
    k_hist<<<nb_E, T, 0, s1>>>(dst, cnt, E);
    k_scan_a<<<nb_scan, T, 0, s1>>>(cnt, rowptr, bsum, dis, n);
    k_scan_b<<<1, 32, 0, s1>>>(bsum, nb_scan);
    k_scan_c<<<nb_n, T, 0, s1>>>(rowptr, bsum, n, E);
    k_zero<<<nb_n, T, 0, s1>>>(cnt, n);
    k_fill<<<nb_E, T, 0, s1>>>(src, dst, dis, rowptr, cnt, csrc, cnrm, E);

    cudaEventRecord(evJoin, s1);
    cudaStreamWaitEvent(0, evJoin, 0);

    // ---- layer 0 gather (needs GEMM0 + CSR)
    k_gather<<<gather_blocks, T>>>(rowptr, csrc, cnrm, dis, B0,
                                   (const float4*)(bs), B1, n);
    // layer 1
    k_gemm_h<<<296, T, SM_BYTES>>>((const float*)B1, Ws + (size_t)H * H,
                                   (float*)B0, n, ntiles);
    k_gather<<<gather_blocks, T>>>(rowptr, csrc, cnrm, dis, B0,
                                   (const float4*)(bs + H), B2, n);
    // layer 2 (+ fused final projection)
    k_gemm_h<<<296, T, SM_BYTES>>>((const float*)B2, Ws + (size_t)2 * H * H,
                                   (float*)B0, n, ntiles);
    k_gather_final<<<gather_blocks, T>>>(rowptr, csrc, cnrm, dis, B0,
                                         (const float4*)(bs + 2 * H),
                                         (const float4*)Wl, bl, (float*)d_out, n);
}